// round 12
// baseline (speedup 1.0000x reference)
#include <cuda_runtime.h>
#include <cstdint>

typedef long long ll;

#define BATCH 8192
#define INS   1024
#define GG    1024
#define HS    2048
#define KTOT  2048

#define BM 128
#define BN 256
#define BK 32
#define NKI (KTOT/BK)     // 64 K-stages
#define STAGES 4

#define A_BYTES (BM*BK*4)     // 16384
#define B_BYTES (BN*BK*4)     // 32768
#define A_OFF  1024
#define B_OFF  (A_OFF + STAGES*A_BYTES)
#define SMEM_TOTAL (B_OFF + STAGES*B_BYTES)   // 197632

#define SW(o) ((o) ^ (((o)>>3)&0x70))

// ---------------- scratch ----------------
__device__ float g_HA[(size_t)BATCH * GG];   // h2_fl, later h1_fl
__device__ float g_HB[(size_t)BATCH * GG];   // r * h_fl
__device__ float g_Z [(size_t)BATCH * GG];   // z1, later z2
__device__ float g_WT[(size_t)KTOT * HS];    // transposed weight [N][K]
__device__ double g_bp1[512];
__device__ double g_bp2[512];

// ---------------- helpers ----------------
__device__ __forceinline__ uint32_t smaddr(const void* p) {
    return (uint32_t)__cvta_generic_to_shared(p);
}
__device__ __forceinline__ void cp16(uint32_t d, const void* s) {
    asm volatile("cp.async.cg.shared.global [%0], [%1], 16;\n" :: "r"(d), "l"(s));
}
__device__ __forceinline__ void cpcommit() { asm volatile("cp.async.commit_group;\n" ::); }
template<int N> __device__ __forceinline__ void cpwait() {
    asm volatile("cp.async.wait_group %0;\n" :: "n"(N));
}

// ldmatrix x4 over 16B row segments; for f32 data each 8x8 b16 matrix is an
// 8-row x 4-f32 block and thread t receives element [t/4][t%4] — exactly the
// tf32 mma fragment layout (CUTLASS tf32-LDSM trick, sm_75+).
__device__ __forceinline__ void ldsm4(uint32_t* r, uint32_t addr) {
    asm volatile("ldmatrix.sync.aligned.m8n8.x4.shared.b16 {%0,%1,%2,%3}, [%4];"
        : "=r"(r[0]), "=r"(r[1]), "=r"(r[2]), "=r"(r[3]) : "r"(addr));
}

// legacy m16n8k8 tf32 mma (valid on base sm_103 target)
__device__ __forceinline__ void mma_tf32(float* d, const uint32_t* a, const uint32_t* b) {
    asm volatile(
        "mma.sync.aligned.m16n8k8.row.col.f32.tf32.tf32.f32 "
        "{%0,%1,%2,%3}, {%4,%5,%6,%7}, {%8,%9}, {%0,%1,%2,%3};\n"
        : "+f"(d[0]), "+f"(d[1]), "+f"(d[2]), "+f"(d[3])
        : "r"(a[0]), "r"(a[1]), "r"(a[2]), "r"(a[3]), "r"(b[0]), "r"(b[1]));
}

__device__ __forceinline__ float sigf(float v) { return 1.0f / (1.0f + expf(-v)); }
__device__ __forceinline__ void hupd(float pre, float z, int h, float* rec, float* oh) {
    float gv = tanhf(pre);
    ll zf = (ll)(z * 1024.0f); if (zf < 1) zf = 1;
    int hi = (int)((((ll)h * zf) >> 10) + (ll)((1.0f - z) * gv * 8388608.0f));
    *rec = (float)hi; *oh = (float)hi * (1.0f / 8388608.0f);
}

// ---------------- GEMM ----------------
// Identical smem layout / pipeline / epilogue to the proven round-11 kernel;
// only the fragment loads changed: LDS.32 x128/kt -> LDSM.x4 x32/kt.
template<int EPI>
__global__ void __launch_bounds__(256, 1) gemm_tc(
    const float* __restrict__ x,
    const float* __restrict__ bias,
    int hinSel,
    const int* __restrict__ hidden,
    int hoff,
    float* __restrict__ out,
    int writeHA)
{
    extern __shared__ char smem[];
    const uint32_t sbase = smaddr(smem);
    const int tid  = threadIdx.x;
    const int wid  = tid >> 5, lane = tid & 31;
    const int bm0  = blockIdx.y * BM;
    const int bn0  = blockIdx.x * BN;
    const float* Hin = hinSel ? g_HB : g_HA;

    auto load_stage = [&](int kt, int buf) {
        const int kbase = kt * BK;
        const float* asrc = (kbase < INS) ? (x + kbase) : (Hin + (kbase - INS));
        const uint32_t abase = sbase + A_OFF + buf * A_BYTES;
        #pragma unroll
        for (int i = 0; i < 4; ++i) {
            int q = tid + i * 256;
            int row = q >> 3, kc = q & 7;
            uint32_t off = row * 128 + kc * 16;
            cp16(abase + SW(off), asrc + (size_t)(bm0 + row) * INS + kc * 4);
        }
        const uint32_t bbase = sbase + B_OFF + buf * B_BYTES;
        #pragma unroll
        for (int i = 0; i < 8; ++i) {
            int q = tid + i * 256;
            int row = q >> 3, kc = q & 7;
            uint32_t off = row * 128 + kc * 16;
            cp16(bbase + SW(off), g_WT + (size_t)(bn0 + row) * KTOT + kbase + kc * 4);
        }
    };

    #pragma unroll
    for (int s = 0; s < STAGES - 1; ++s) { load_stage(s, s); cpcommit(); }

    // 8 warps: 2(M) x 4(N); warp tile 64x64
    const int wm0 = (wid >> 2) * 64;
    const int wn0 = (wid & 3) * 64;
    const int rm = lane >> 2;

    // ldmatrix lane roles: group g = lane>>3 picks (row-block, k-seg)
    const int r8   = lane & 7;
    const int gsel = lane >> 3;
    // A: g0:(m,k0) g1:(m+8,k0) g2:(m,k0+16B) g3:(m+8,k0+16B)
    const int a_row = wm0 + r8 + ((gsel & 1) << 3);
    const uint32_t a_kx = (uint32_t)((gsel >> 1) << 4);
    // B: g0:(n,k0) g1:(n,k0+16B) g2:(n+8,k0) g3:(n+8,k0+16B)
    const int b_row = wn0 + r8 + ((gsel >> 1) << 3);
    const uint32_t b_kx = (uint32_t)((gsel & 1) << 4);
    const uint32_t lsw = (uint32_t)(r8 << 4);      // row&7 is r8 for both A and B
    const uint32_t aAddr0 = sbase + A_OFF + (uint32_t)(a_row * 128);
    const uint32_t bAddr0 = sbase + B_OFF + (uint32_t)(b_row * 128);

    float acc[4][8][4];
    #pragma unroll
    for (int i = 0; i < 4; ++i)
        #pragma unroll
        for (int j = 0; j < 8; ++j)
            #pragma unroll
            for (int e = 0; e < 4; ++e) acc[i][j][e] = 0.0f;

    for (int kt = 0; kt < NKI; ++kt) {
        const int buf = kt & (STAGES - 1);
        const int lt = kt + STAGES - 1;
        if (lt < NKI) load_stage(lt, lt & (STAGES - 1));
        cpcommit();
        cpwait<STAGES - 1>();
        __syncthreads();

        const uint32_t abuf = aAddr0 + buf * A_BYTES;
        const uint32_t bbuf = bAddr0 + buf * B_BYTES;
        #pragma unroll
        for (int ks = 0; ks < 4; ++ks) {
            const uint32_t ksa = ((uint32_t)(ks * 32) + a_kx) ^ lsw;
            const uint32_t ksb = ((uint32_t)(ks * 32) + b_kx) ^ lsw;
            uint32_t af[4][4];
            #pragma unroll
            for (int mi = 0; mi < 4; ++mi)
                ldsm4(af[mi], abuf + mi * 2048 + ksa);
            uint32_t bf[4][4];   // bf[p] = {b(2p)[0], b(2p)[1], b(2p+1)[0], b(2p+1)[1]}
            #pragma unroll
            for (int p = 0; p < 4; ++p)
                ldsm4(bf[p], bbuf + p * 2048 + ksb);
            #pragma unroll
            for (int p = 0; p < 4; ++p) {
                #pragma unroll
                for (int mi = 0; mi < 4; ++mi)
                    mma_tf32(acc[mi][2 * p], af[mi], &bf[p][0]);
                #pragma unroll
                for (int mi = 0; mi < 4; ++mi)
                    mma_tf32(acc[mi][2 * p + 1], af[mi], &bf[p][2]);
            }
        }
        __syncthreads();
    }

    // ---- epilogue (round-11 form, unchanged) ----
    const int c2 = (lane & 3) * 2;
    #pragma unroll
    for (int mi = 0; mi < 4; ++mi) {
        #pragma unroll
        for (int rr = 0; rr < 2; ++rr) {
            int m = bm0 + wm0 + mi * 16 + rm + rr * 8;
            #pragma unroll
            for (int ni = 0; ni < 8; ++ni) {
                int n = bn0 + wn0 + ni * 8 + c2;
                float p0 = acc[mi][ni][rr * 2 + 0] + bias[n];
                float p1 = acc[mi][ni][rr * 2 + 1] + bias[n + 1];
                if (EPI == 0) {
                    float s0 = sigf(p0), s1 = sigf(p1);
                    if (n < GG) {
                        float2 z; z.x = 0.875f * s0 + 0.125f; z.y = 0.875f * s1 + 0.125f;
                        *(float2*)&g_Z[(size_t)m * GG + n] = z;
                    } else {
                        size_t j = (size_t)m * GG + (n - GG);
                        float2 ha = *(const float2*)&g_HA[j];
                        float2 hb; hb.x = s0 * ha.x; hb.y = s1 * ha.y;
                        *(float2*)&g_HB[j] = hb;
                    }
                } else {
                    size_t zj = (size_t)m * GG + n;
                    float2 zv = *(const float2*)&g_Z[zj];
                    int2 hv = *(const int2*)&hidden[(size_t)m * HS + hoff + n];
                    float2 recf, ohf;
                    hupd(p0, zv.x, hv.x, &recf.x, &ohf.x);
                    hupd(p1, zv.y, hv.y, &recf.y, &ohf.y);
                    *(float2*)&out[(size_t)m * HS + hoff + n] = recf;
                    *(float2*)&out[(size_t)BATCH * HS + (size_t)m * HS + hoff + n] = ohf;
                    if (writeHA) *(float2*)&g_HA[zj] = ohf;
                }
            }
        }
    }
}

// ---------------- aux kernels ----------------
// WT[n][k] = W[k][n]
__global__ void transpose_k(const float* __restrict__ W, int N, int which) {
    __shared__ float t[32][33];
    int n0 = blockIdx.x * 32, k0 = blockIdx.y * 32;
    int tx = threadIdx.x, ty = threadIdx.y;   // 32 x 8
    (void)which;
    #pragma unroll
    for (int i = 0; i < 32; i += 8)
        t[ty + i][tx] = W[(size_t)(k0 + ty + i) * N + n0 + tx];
    __syncthreads();
    #pragma unroll
    for (int i = 0; i < 32; i += 8)
        g_WT[(size_t)(n0 + ty + i) * KTOT + k0 + tx] = t[tx][ty + i];
}

// second transpose buffer so two weight matrices can be staged at once
__device__ float g_WT2[(size_t)KTOT * GG];
__global__ void transpose2_k(const float* __restrict__ W, int N) {
    __shared__ float t[32][33];
    int n0 = blockIdx.x * 32, k0 = blockIdx.y * 32;
    int tx = threadIdx.x, ty = threadIdx.y;
    #pragma unroll
    for (int i = 0; i < 32; i += 8)
        t[ty + i][tx] = W[(size_t)(k0 + ty + i) * N + n0 + tx];
    __syncthreads();
    #pragma unroll
    for (int i = 0; i < 32; i += 8)
        g_WT2[(size_t)(n0 + ty + i) * KTOT + k0 + tx] = t[tx][ty + i];
}
// copy WT2 -> WT (g-gemm weights staged early, moved before use)
__global__ void copy_wt_k() {
    size_t N4 = (size_t)KTOT * GG / 4;
    for (size_t i = (size_t)blockIdx.x * blockDim.x + threadIdx.x; i < N4;
         i += (size_t)gridDim.x * blockDim.x) {
        *(float4*)&g_WT[i * 4] = *(const float4*)&g_WT2[i * 4];
    }
}

// HA = h2_fl = hidden[:, G:] / 2^23  (vectorized int4 -> float4)
__global__ void prep_k(const int* __restrict__ hidden) {
    size_t N4 = (size_t)BATCH * GG / 4;
    for (size_t i = (size_t)blockIdx.x * blockDim.x + threadIdx.x; i < N4;
         i += (size_t)gridDim.x * blockDim.x) {
        size_t row = i >> 8;
        int c4 = (int)(i & 255) * 4;
        int4 h = *(const int4*)&hidden[row * HS + GG + c4];
        float4 f;
        f.x = (float)h.x * (1.0f / 8388608.0f);
        f.y = (float)h.y * (1.0f / 8388608.0f);
        f.z = (float)h.z * (1.0f / 8388608.0f);
        f.w = (float)h.w * (1.0f / 8388608.0f);
        *(float4*)&g_HA[i * 4] = f;
    }
}

// -log2(z) reduction; float inner accumulator, double combine.
__global__ void bits_k(const int* __restrict__ slice_ptr, int which) {
    const int slice = slice_ptr ? __ldg(slice_ptr) : 0;
    float s = 0.0f;
    size_t N4 = (size_t)BATCH * GG / 4;
    for (size_t i = (size_t)blockIdx.x * blockDim.x + threadIdx.x; i < N4;
         i += (size_t)gridDim.x * blockDim.x) {
        int col = (int)(i & 255) * 4;
        float4 z = *(const float4*)&g_Z[i * 4];
        if (col     >= slice) s -= log2f(z.x);
        if (col + 1 >= slice) s -= log2f(z.y);
        if (col + 2 >= slice) s -= log2f(z.z);
        if (col + 3 >= slice) s -= log2f(z.w);
    }
    #pragma unroll
    for (int o = 16; o > 0; o >>= 1)
        s += __shfl_down_sync(0xFFFFFFFFu, s, o);
    __shared__ double sm[8];
    int wid = threadIdx.x >> 5, lane = threadIdx.x & 31;
    if (lane == 0) sm[wid] = (double)s;
    __syncthreads();
    if (threadIdx.x == 0) {
        double t = 0.0;
        #pragma unroll
        for (int i = 0; i < 8; ++i) t += sm[i];
        if (which) g_bp2[blockIdx.x] = t;
        else       g_bp1[blockIdx.x] = t;
    }
}

__global__ void final_k(float* __restrict__ out, const int* __restrict__ slice_ptr) {
    __shared__ double sm[256];
    double s = 0.0;
    for (int i = threadIdx.x; i < 512; i += 256) s += g_bp1[i] + g_bp2[i];
    sm[threadIdx.x] = s;
    __syncthreads();
    for (int o = 128; o > 0; o >>= 1) {
        if (threadIdx.x < (unsigned)o) sm[threadIdx.x] += sm[threadIdx.x + o];
        __syncthreads();
    }
    if (threadIdx.x == 0) {
        int slice = slice_ptr ? slice_ptr[0] : 0;
        out[(size_t)2 * BATCH * HS] =
            (float)(sm[0] + 32.0 * (double)slice * (double)BATCH);
    }
}

extern "C" void kernel_launch(void* const* d_in, const int* in_sizes, int n_in,
                              void* d_out, int out_size) {
    (void)in_sizes; (void)out_size;
    const float* x      = (const float*)d_in[0];
    const int*   hidden = (const int*)d_in[1];
    const float* Wzr1   = (const float*)d_in[2];
    const float* bzr1   = (const float*)d_in[3];
    const float* Wg1    = (const float*)d_in[4];
    const float* bg1    = (const float*)d_in[5];
    const float* Wzr2   = (const float*)d_in[6];
    const float* bzr2   = (const float*)d_in[7];
    const float* Wg2    = (const float*)d_in[8];
    const float* bg2    = (const float*)d_in[9];
    const int*   slice  = (n_in > 10) ? (const int*)d_in[10] : nullptr;
    float* out = (float*)d_out;

    cudaFuncSetAttribute(gemm_tc<0>, cudaFuncAttributeMaxDynamicSharedMemorySize, SMEM_TOTAL);
    cudaFuncSetAttribute(gemm_tc<1>, cudaFuncAttributeMaxDynamicSharedMemorySize, SMEM_TOTAL);

    // Launch order puts the first zr-GEMM at index 3 — the launch the
    // profiler has consistently captured across rounds.
    prep_k<<<2048, 256>>>(hidden);                                   // 0
    transpose_k<<<dim3(64, 64), dim3(32, 8)>>>(Wzr1, HS, 0);         // 1
    transpose2_k<<<dim3(32, 64), dim3(32, 8)>>>(Wg1, GG);            // 2

    // zr1: z1 -> g_Z, HB = r1*HA
    gemm_tc<0><<<dim3(HS / BN, BATCH / BM), 256, SMEM_TOTAL>>>(      // 3 (profiled)
        x, bzr1, 0, nullptr, 0, nullptr, 0);
    bits_k<<<512, 256>>>(slice, 0);                                  // 4
    copy_wt_k<<<1024, 256>>>();                                      // 5  WT <- Wg1^T

    // g1: h1 update; rec/out cols [0,1024); HA = h1_fl
    gemm_tc<1><<<dim3(GG / BN, BATCH / BM), 256, SMEM_TOTAL>>>(      // 6
        x, bg1, 1, hidden, 0, out, 1);

    // zr2
    transpose_k<<<dim3(64, 64), dim3(32, 8)>>>(Wzr2, HS, 0);         // 7
    gemm_tc<0><<<dim3(HS / BN, BATCH / BM), 256, SMEM_TOTAL>>>(      // 8
        x, bzr2, 0, nullptr, 0, nullptr, 0);
    bits_k<<<512, 256>>>(nullptr, 1);                                // 9

    // g2
    transpose_k<<<dim3(32, 64), dim3(32, 8)>>>(Wg2, GG, 0);          // 10
    gemm_tc<1><<<dim3(GG / BN, BATCH / BM), 256, SMEM_TOTAL>>>(      // 11
        x, bg2, 1, hidden, 1024, out, 0);

    final_k<<<1, 256>>>(out, slice);                                 // 12
}

// round 14
// speedup vs baseline: 1.0724x; 1.0724x over previous
#include <cuda_runtime.h>
#include <cstdint>

typedef long long ll;

#define BATCH 8192
#define INS   1024
#define GG    1024
#define HS    2048
#define KTOT  2048

#define BM 128
#define BN 256
#define BK 32
#define NKI (KTOT/BK)     // 64 K-stages
#define STAGES 4
#define NTHR 512          // 16 warps: 2(M) x 8(N), warp tile 64x32

#define A_BYTES (BM*BK*4)     // 16384
#define B_BYTES (BN*BK*4)     // 32768
#define A_OFF  1024
#define B_OFF  (A_OFF + STAGES*A_BYTES)
#define SMEM_TOTAL (B_OFF + STAGES*B_BYTES)   // 197632

#define SW(o) ((o) ^ (((o)>>3)&0x70))

// ---------------- scratch ----------------
__device__ float g_HA[(size_t)BATCH * GG];   // h2_fl, later h1_fl
__device__ float g_HB[(size_t)BATCH * GG];   // r * h_fl
__device__ float g_Z [(size_t)BATCH * GG];   // z1, later z2
__device__ float g_WT[(size_t)KTOT * HS];    // transposed weight [N][K]
__device__ float g_WT2[(size_t)KTOT * GG];   // staging buffer
__device__ double g_bp1[512];
__device__ double g_bp2[512];

// ---------------- helpers ----------------
__device__ __forceinline__ uint32_t smaddr(const void* p) {
    return (uint32_t)__cvta_generic_to_shared(p);
}
__device__ __forceinline__ void cp16(uint32_t d, const void* s) {
    asm volatile("cp.async.cg.shared.global [%0], [%1], 16;\n" :: "r"(d), "l"(s));
}
__device__ __forceinline__ void cpcommit() { asm volatile("cp.async.commit_group;\n" ::); }
template<int N> __device__ __forceinline__ void cpwait() {
    asm volatile("cp.async.wait_group %0;\n" :: "n"(N));
}

// ldmatrix x4 over 16B row segments (tf32-LDSM trick: thread t gets [t/4][t%4]
// of each 8x4-f32 block = exact tf32 mma fragment layout)
__device__ __forceinline__ void ldsm4(uint32_t* r, uint32_t addr) {
    asm volatile("ldmatrix.sync.aligned.m8n8.x4.shared.b16 {%0,%1,%2,%3}, [%4];"
        : "=r"(r[0]), "=r"(r[1]), "=r"(r[2]), "=r"(r[3]) : "r"(addr));
}

// legacy m16n8k8 tf32 mma (valid on base sm_103 target)
__device__ __forceinline__ void mma_tf32(float* d, const uint32_t* a, const uint32_t* b) {
    asm volatile(
        "mma.sync.aligned.m16n8k8.row.col.f32.tf32.tf32.f32 "
        "{%0,%1,%2,%3}, {%4,%5,%6,%7}, {%8,%9}, {%0,%1,%2,%3};\n"
        : "+f"(d[0]), "+f"(d[1]), "+f"(d[2]), "+f"(d[3])
        : "r"(a[0]), "r"(a[1]), "r"(a[2]), "r"(a[3]), "r"(b[0]), "r"(b[1]));
}

__device__ __forceinline__ float sigf(float v) { return 1.0f / (1.0f + expf(-v)); }
__device__ __forceinline__ void hupd(float pre, float z, int h, float* rec, float* oh) {
    float gv = tanhf(pre);
    ll zf = (ll)(z * 1024.0f); if (zf < 1) zf = 1;
    int hi = (int)((((ll)h * zf) >> 10) + (ll)((1.0f - z) * gv * 8388608.0f));
    *rec = (float)hi; *oh = (float)hi * (1.0f / 8388608.0f);
}

// ---------------- GEMM ----------------
// Same CTA tile/pipeline as round 12; thread count 256 -> 512 (16 warps,
// warp tile 64x32) so 4 warps/SMSP cover HMMA/LDSM/BAR latency; acc halves
// to 64 regs/thread and launch_bounds caps regs at 128 (full RF, 1 CTA).
template<int EPI>
__global__ void __launch_bounds__(NTHR, 1) gemm_tc(
    const float* __restrict__ x,
    const float* __restrict__ bias,
    int hinSel,
    const int* __restrict__ hidden,
    int hoff,
    float* __restrict__ out,
    int writeHA)
{
    extern __shared__ char smem[];
    const uint32_t sbase = smaddr(smem);
    const int tid  = threadIdx.x;
    const int wid  = tid >> 5, lane = tid & 31;
    const int bm0  = blockIdx.y * BM;
    const int bn0  = blockIdx.x * BN;
    const float* Hin = hinSel ? g_HB : g_HA;

    auto load_stage = [&](int kt, int buf) {
        const int kbase = kt * BK;
        const float* asrc = (kbase < INS) ? (x + kbase) : (Hin + (kbase - INS));
        const uint32_t abase = sbase + A_OFF + buf * A_BYTES;
        #pragma unroll
        for (int i = 0; i < 2; ++i) {
            int q = tid + i * NTHR;
            int row = q >> 3, kc = q & 7;
            uint32_t off = row * 128 + kc * 16;
            cp16(abase + SW(off), asrc + (size_t)(bm0 + row) * INS + kc * 4);
        }
        const uint32_t bbase = sbase + B_OFF + buf * B_BYTES;
        #pragma unroll
        for (int i = 0; i < 4; ++i) {
            int q = tid + i * NTHR;
            int row = q >> 3, kc = q & 7;
            uint32_t off = row * 128 + kc * 16;
            cp16(bbase + SW(off), g_WT + (size_t)(bn0 + row) * KTOT + kbase + kc * 4);
        }
    };

    #pragma unroll
    for (int s = 0; s < STAGES - 1; ++s) { load_stage(s, s); cpcommit(); }

    // 16 warps: 2(M) x 8(N); warp tile 64x32
    const int wm0 = (wid >> 3) * 64;
    const int wn0 = (wid & 7) * 32;
    const int rm = lane >> 2;

    // ldmatrix lane roles (as round 12)
    const int r8   = lane & 7;
    const int gsel = lane >> 3;
    const int a_row = wm0 + r8 + ((gsel & 1) << 3);
    const uint32_t a_kx = (uint32_t)((gsel >> 1) << 4);
    const int b_row = wn0 + r8 + ((gsel >> 1) << 3);
    const uint32_t b_kx = (uint32_t)((gsel & 1) << 4);
    const uint32_t lsw = (uint32_t)(r8 << 4);
    const uint32_t aAddr0 = sbase + A_OFF + (uint32_t)(a_row * 128);
    const uint32_t bAddr0 = sbase + B_OFF + (uint32_t)(b_row * 128);

    float acc[4][4][4];
    #pragma unroll
    for (int i = 0; i < 4; ++i)
        #pragma unroll
        for (int j = 0; j < 4; ++j)
            #pragma unroll
            for (int e = 0; e < 4; ++e) acc[i][j][e] = 0.0f;

    for (int kt = 0; kt < NKI; ++kt) {
        const int buf = kt & (STAGES - 1);
        const int lt = kt + STAGES - 1;
        if (lt < NKI) load_stage(lt, lt & (STAGES - 1));
        cpcommit();
        cpwait<STAGES - 1>();
        __syncthreads();

        const uint32_t abuf = aAddr0 + buf * A_BYTES;
        const uint32_t bbuf = bAddr0 + buf * B_BYTES;
        #pragma unroll
        for (int ks = 0; ks < 4; ++ks) {
            const uint32_t ksa = ((uint32_t)(ks * 32) + a_kx) ^ lsw;
            const uint32_t ksb = ((uint32_t)(ks * 32) + b_kx) ^ lsw;
            uint32_t af[4][4];
            #pragma unroll
            for (int mi = 0; mi < 4; ++mi)
                ldsm4(af[mi], abuf + mi * 2048 + ksa);
            uint32_t bf[2][4];   // bf[p] = {b(2p)[0..1], b(2p+1)[0..1]}
            #pragma unroll
            for (int p = 0; p < 2; ++p)
                ldsm4(bf[p], bbuf + p * 2048 + ksb);
            #pragma unroll
            for (int p = 0; p < 2; ++p) {
                #pragma unroll
                for (int mi = 0; mi < 4; ++mi)
                    mma_tf32(acc[mi][2 * p], af[mi], &bf[p][0]);
                #pragma unroll
                for (int mi = 0; mi < 4; ++mi)
                    mma_tf32(acc[mi][2 * p + 1], af[mi], &bf[p][2]);
            }
        }
        __syncthreads();
    }

    // ---- epilogue (same math/order per element as rounds 3/11/12) ----
    const int c2 = (lane & 3) * 2;
    #pragma unroll
    for (int mi = 0; mi < 4; ++mi) {
        #pragma unroll
        for (int rr = 0; rr < 2; ++rr) {
            int m = bm0 + wm0 + mi * 16 + rm + rr * 8;
            #pragma unroll
            for (int ni = 0; ni < 4; ++ni) {
                int n = bn0 + wn0 + ni * 8 + c2;
                float p0 = acc[mi][ni][rr * 2 + 0] + bias[n];
                float p1 = acc[mi][ni][rr * 2 + 1] + bias[n + 1];
                if (EPI == 0) {
                    float s0 = sigf(p0), s1 = sigf(p1);
                    if (n < GG) {
                        float2 z; z.x = 0.875f * s0 + 0.125f; z.y = 0.875f * s1 + 0.125f;
                        *(float2*)&g_Z[(size_t)m * GG + n] = z;
                    } else {
                        size_t j = (size_t)m * GG + (n - GG);
                        float2 ha = *(const float2*)&g_HA[j];
                        float2 hb; hb.x = s0 * ha.x; hb.y = s1 * ha.y;
                        *(float2*)&g_HB[j] = hb;
                    }
                } else {
                    size_t zj = (size_t)m * GG + n;
                    float2 zv = *(const float2*)&g_Z[zj];
                    int2 hv = *(const int2*)&hidden[(size_t)m * HS + hoff + n];
                    float2 recf, ohf;
                    hupd(p0, zv.x, hv.x, &recf.x, &ohf.x);
                    hupd(p1, zv.y, hv.y, &recf.y, &ohf.y);
                    *(float2*)&out[(size_t)m * HS + hoff + n] = recf;
                    *(float2*)&out[(size_t)BATCH * HS + (size_t)m * HS + hoff + n] = ohf;
                    if (writeHA) *(float2*)&g_HA[zj] = ohf;
                }
            }
        }
    }
}

// ---------------- aux kernels ----------------
__global__ void transpose_k(const float* __restrict__ W, int N) {
    __shared__ float t[32][33];
    int n0 = blockIdx.x * 32, k0 = blockIdx.y * 32;
    int tx = threadIdx.x, ty = threadIdx.y;   // 32 x 8
    #pragma unroll
    for (int i = 0; i < 32; i += 8)
        t[ty + i][tx] = W[(size_t)(k0 + ty + i) * N + n0 + tx];
    __syncthreads();
    #pragma unroll
    for (int i = 0; i < 32; i += 8)
        g_WT[(size_t)(n0 + ty + i) * KTOT + k0 + tx] = t[tx][ty + i];
}

__global__ void transpose2_k(const float* __restrict__ W, int N) {
    __shared__ float t[32][33];
    int n0 = blockIdx.x * 32, k0 = blockIdx.y * 32;
    int tx = threadIdx.x, ty = threadIdx.y;
    #pragma unroll
    for (int i = 0; i < 32; i += 8)
        t[ty + i][tx] = W[(size_t)(k0 + ty + i) * N + n0 + tx];
    __syncthreads();
    #pragma unroll
    for (int i = 0; i < 32; i += 8)
        g_WT2[(size_t)(n0 + ty + i) * KTOT + k0 + tx] = t[tx][ty + i];
}
__global__ void copy_wt_k() {
    size_t N4 = (size_t)KTOT * GG / 4;
    for (size_t i = (size_t)blockIdx.x * blockDim.x + threadIdx.x; i < N4;
         i += (size_t)gridDim.x * blockDim.x) {
        *(float4*)&g_WT[i * 4] = *(const float4*)&g_WT2[i * 4];
    }
}

__global__ void prep_k(const int* __restrict__ hidden) {
    size_t N4 = (size_t)BATCH * GG / 4;
    for (size_t i = (size_t)blockIdx.x * blockDim.x + threadIdx.x; i < N4;
         i += (size_t)gridDim.x * blockDim.x) {
        size_t row = i >> 8;
        int c4 = (int)(i & 255) * 4;
        int4 h = *(const int4*)&hidden[row * HS + GG + c4];
        float4 f;
        f.x = (float)h.x * (1.0f / 8388608.0f);
        f.y = (float)h.y * (1.0f / 8388608.0f);
        f.z = (float)h.z * (1.0f / 8388608.0f);
        f.w = (float)h.w * (1.0f / 8388608.0f);
        *(float4*)&g_HA[i * 4] = f;
    }
}

__global__ void bits_k(const int* __restrict__ slice_ptr, int which) {
    const int slice = slice_ptr ? __ldg(slice_ptr) : 0;
    float s = 0.0f;
    size_t N4 = (size_t)BATCH * GG / 4;
    for (size_t i = (size_t)blockIdx.x * blockDim.x + threadIdx.x; i < N4;
         i += (size_t)gridDim.x * blockDim.x) {
        int col = (int)(i & 255) * 4;
        float4 z = *(const float4*)&g_Z[i * 4];
        if (col     >= slice) s -= log2f(z.x);
        if (col + 1 >= slice) s -= log2f(z.y);
        if (col + 2 >= slice) s -= log2f(z.z);
        if (col + 3 >= slice) s -= log2f(z.w);
    }
    #pragma unroll
    for (int o = 16; o > 0; o >>= 1)
        s += __shfl_down_sync(0xFFFFFFFFu, s, o);
    __shared__ double sm[8];
    int wid = threadIdx.x >> 5, lane = threadIdx.x & 31;
    if (lane == 0) sm[wid] = (double)s;
    __syncthreads();
    if (threadIdx.x == 0) {
        double t = 0.0;
        #pragma unroll
        for (int i = 0; i < 8; ++i) t += sm[i];
        if (which) g_bp2[blockIdx.x] = t;
        else       g_bp1[blockIdx.x] = t;
    }
}

__global__ void final_k(float* __restrict__ out, const int* __restrict__ slice_ptr) {
    __shared__ double sm[256];
    double s = 0.0;
    for (int i = threadIdx.x; i < 512; i += 256) s += g_bp1[i] + g_bp2[i];
    sm[threadIdx.x] = s;
    __syncthreads();
    for (int o = 128; o > 0; o >>= 1) {
        if (threadIdx.x < (unsigned)o) sm[threadIdx.x] += sm[threadIdx.x + o];
        __syncthreads();
    }
    if (threadIdx.x == 0) {
        int slice = slice_ptr ? slice_ptr[0] : 0;
        out[(size_t)2 * BATCH * HS] =
            (float)(sm[0] + 32.0 * (double)slice * (double)BATCH);
    }
}

extern "C" void kernel_launch(void* const* d_in, const int* in_sizes, int n_in,
                              void* d_out, int out_size) {
    (void)in_sizes; (void)out_size;
    const float* x      = (const float*)d_in[0];
    const int*   hidden = (const int*)d_in[1];
    const float* Wzr1   = (const float*)d_in[2];
    const float* bzr1   = (const float*)d_in[3];
    const float* Wg1    = (const float*)d_in[4];
    const float* bg1    = (const float*)d_in[5];
    const float* Wzr2   = (const float*)d_in[6];
    const float* bzr2   = (const float*)d_in[7];
    const float* Wg2    = (const float*)d_in[8];
    const float* bg2    = (const float*)d_in[9];
    const int*   slice  = (n_in > 10) ? (const int*)d_in[10] : nullptr;
    float* out = (float*)d_out;

    cudaFuncSetAttribute(gemm_tc<0>, cudaFuncAttributeMaxDynamicSharedMemorySize, SMEM_TOTAL);
    cudaFuncSetAttribute(gemm_tc<1>, cudaFuncAttributeMaxDynamicSharedMemorySize, SMEM_TOTAL);

    // first zr-GEMM stays at launch index 3 (the launch ncu captures)
    prep_k<<<2048, 256>>>(hidden);                                   // 0
    transpose_k<<<dim3(64, 64), dim3(32, 8)>>>(Wzr1, HS);            // 1
    transpose2_k<<<dim3(32, 64), dim3(32, 8)>>>(Wg1, GG);            // 2

    gemm_tc<0><<<dim3(HS / BN, BATCH / BM), NTHR, SMEM_TOTAL>>>(     // 3 (profiled)
        x, bzr1, 0, nullptr, 0, nullptr, 0);
    bits_k<<<512, 256>>>(slice, 0);                                  // 4
    copy_wt_k<<<1024, 256>>>();                                      // 5

    gemm_tc<1><<<dim3(GG / BN, BATCH / BM), NTHR, SMEM_TOTAL>>>(     // 6
        x, bg1, 1, hidden, 0, out, 1);

    transpose_k<<<dim3(64, 64), dim3(32, 8)>>>(Wzr2, HS);            // 7
    gemm_tc<0><<<dim3(HS / BN, BATCH / BM), NTHR, SMEM_TOTAL>>>(     // 8
        x, bzr2, 0, nullptr, 0, nullptr, 0);
    bits_k<<<512, 256>>>(nullptr, 1);                                // 9

    transpose_k<<<dim3(32, 64), dim3(32, 8)>>>(Wg2, GG);             // 10
    gemm_tc<1><<<dim3(GG / BN, BATCH / BM), NTHR, SMEM_TOTAL>>>(     // 11
        x, bg2, 1, hidden, 1024, out, 0);

    final_k<<<1, 256>>>(out, slice);                                 // 12
}

// round 16
// speedup vs baseline: 1.7648x; 1.6456x over previous
#include <cuda_runtime.h>
#include <cuda_fp16.h>
#include <cstdint>

typedef long long ll;

#define BATCH 8192
#define INS   1024          // K-halves from x
#define GG    1024
#define HS    2048
#define KTOT  2048          // total K (halves)

#define BM 128
#define BN 256
#define BK 64               // halves per stage = 128 bytes per row (same geometry)
#define NKI (KTOT/BK)       // 32 K-stages
#define STAGES 4
#define NTHR 512            // 16 warps: 2(M) x 8(N), warp tile 64x32

#define A_BYTES (BM*BK*2)   // 16384
#define B_BYTES (BN*BK*2)   // 32768
#define A_OFF  1024
#define B_OFF  (A_OFF + STAGES*A_BYTES)
#define SMEM_TOTAL (B_OFF + STAGES*B_BYTES)   // 197632

#define SW(o) ((o) ^ (((o)>>3)&0x70))

// ---------------- scratch ----------------
__device__ float  g_HA [(size_t)BATCH * GG];   // f32 master: h2_fl, later h1_fl
__device__ __half g_HAH[(size_t)BATCH * GG];   // f16 mirror for GEMM A-loads
__device__ __half g_HBH[(size_t)BATCH * GG];   // f16: r * h_fl (single rounding)
__device__ __half g_XH [(size_t)BATCH * INS];  // f16 x
__device__ float  g_Z  [(size_t)BATCH * GG];   // z1, later z2
__device__ __half g_WTH[(size_t)KTOT * HS];    // transposed weight [N][K] f16
__device__ double g_bp1[512];
__device__ double g_bp2[512];

// ---------------- helpers ----------------
__device__ __forceinline__ uint32_t smaddr(const void* p) {
    return (uint32_t)__cvta_generic_to_shared(p);
}
__device__ __forceinline__ void cp16(uint32_t d, const void* s) {
    asm volatile("cp.async.cg.shared.global [%0], [%1], 16;\n" :: "r"(d), "l"(s));
}
__device__ __forceinline__ void cpcommit() { asm volatile("cp.async.commit_group;\n" ::); }
template<int N> __device__ __forceinline__ void cpwait() {
    asm volatile("cp.async.wait_group %0;\n" :: "n"(N));
}

// ldmatrix x4: 4 8x8-b16 matrices; thread t gets (row t/4, half-pair t%4)
__device__ __forceinline__ void ldsm4(uint32_t* r, uint32_t addr) {
    asm volatile("ldmatrix.sync.aligned.m8n8.x4.shared.b16 {%0,%1,%2,%3}, [%4];"
        : "=r"(r[0]), "=r"(r[1]), "=r"(r[2]), "=r"(r[3]) : "r"(addr));
}

// f16 inputs, f32 accumulate: K=16 per HMMA (2x tf32 MACs at same issue rate)
__device__ __forceinline__ void mma_f16(float* d, const uint32_t* a, const uint32_t* b) {
    asm volatile(
        "mma.sync.aligned.m16n8k16.row.col.f32.f16.f16.f32 "
        "{%0,%1,%2,%3}, {%4,%5,%6,%7}, {%8,%9}, {%0,%1,%2,%3};\n"
        : "+f"(d[0]), "+f"(d[1]), "+f"(d[2]), "+f"(d[3])
        : "r"(a[0]), "r"(a[1]), "r"(a[2]), "r"(a[3]), "r"(b[0]), "r"(b[1]));
}

__device__ __forceinline__ float sigf(float v) { return 1.0f / (1.0f + expf(-v)); }
__device__ __forceinline__ void hupd(float pre, float z, int h, float* rec, float* oh) {
    float gv = tanhf(pre);
    ll zf = (ll)(z * 1024.0f); if (zf < 1) zf = 1;
    int hi = (int)((((ll)h * zf) >> 10) + (ll)((1.0f - z) * gv * 8388608.0f));
    *rec = (float)hi; *oh = (float)hi * (1.0f / 8388608.0f);
}

// ---------------- GEMM (f16 operands, f32 accum) ----------------
// Structure identical to round 14; BK is 64 halves (same 128B rows, same
// swizzle, same ldmatrix lane roles), mma is m16n8k16.f16.
template<int EPI>
__global__ void __launch_bounds__(NTHR, 1) gemm_tc(
    const float* __restrict__ bias,
    int hinSel,
    const int* __restrict__ hidden,
    int hoff,
    float* __restrict__ out,
    int writeHA)
{
    extern __shared__ char smem[];
    const uint32_t sbase = smaddr(smem);
    const int tid  = threadIdx.x;
    const int wid  = tid >> 5, lane = tid & 31;
    const int bm0  = blockIdx.y * BM;
    const int bn0  = blockIdx.x * BN;
    const __half* HinH = hinSel ? g_HBH : g_HAH;

    auto load_stage = [&](int kt, int buf) {
        const int kbase = kt * BK;
        const __half* asrc = (kbase < INS) ? (g_XH + kbase) : (HinH + (kbase - INS));
        const uint32_t abase = sbase + A_OFF + buf * A_BYTES;
        #pragma unroll
        for (int i = 0; i < 2; ++i) {
            int q = tid + i * NTHR;
            int row = q >> 3, kc = q & 7;
            uint32_t off = row * 128 + kc * 16;
            cp16(abase + SW(off), asrc + (size_t)(bm0 + row) * INS + kc * 8);
        }
        const uint32_t bbase = sbase + B_OFF + buf * B_BYTES;
        #pragma unroll
        for (int i = 0; i < 4; ++i) {
            int q = tid + i * NTHR;
            int row = q >> 3, kc = q & 7;
            uint32_t off = row * 128 + kc * 16;
            cp16(bbase + SW(off), g_WTH + (size_t)(bn0 + row) * KTOT + kbase + kc * 8);
        }
    };

    #pragma unroll
    for (int s = 0; s < STAGES - 1; ++s) { load_stage(s, s); cpcommit(); }

    // 16 warps: 2(M) x 8(N); warp tile 64x32
    const int wm0 = (wid >> 3) * 64;
    const int wn0 = (wid & 7) * 32;
    const int rm = lane >> 2;

    // ldmatrix lane roles (identical to round 14; now chunks are 8 halves)
    const int r8   = lane & 7;
    const int gsel = lane >> 3;
    const int a_row = wm0 + r8 + ((gsel & 1) << 3);
    const uint32_t a_kx = (uint32_t)((gsel >> 1) << 4);
    const int b_row = wn0 + r8 + ((gsel >> 1) << 3);
    const uint32_t b_kx = (uint32_t)((gsel & 1) << 4);
    const uint32_t lsw = (uint32_t)(r8 << 4);
    const uint32_t aAddr0 = sbase + A_OFF + (uint32_t)(a_row * 128);
    const uint32_t bAddr0 = sbase + B_OFF + (uint32_t)(b_row * 128);

    float acc[4][4][4];
    #pragma unroll
    for (int i = 0; i < 4; ++i)
        #pragma unroll
        for (int j = 0; j < 4; ++j)
            #pragma unroll
            for (int e = 0; e < 4; ++e) acc[i][j][e] = 0.0f;

    for (int kt = 0; kt < NKI; ++kt) {
        const int buf = kt & (STAGES - 1);
        const int lt = kt + STAGES - 1;
        if (lt < NKI) load_stage(lt, lt & (STAGES - 1));
        cpcommit();
        cpwait<STAGES - 1>();
        __syncthreads();

        const uint32_t abuf = aAddr0 + buf * A_BYTES;
        const uint32_t bbuf = bAddr0 + buf * B_BYTES;
        #pragma unroll
        for (int ks = 0; ks < 4; ++ks) {        // K=16 halves per ks
            const uint32_t ksa = ((uint32_t)(ks * 32) + a_kx) ^ lsw;
            const uint32_t ksb = ((uint32_t)(ks * 32) + b_kx) ^ lsw;
            uint32_t af[4][4];
            #pragma unroll
            for (int mi = 0; mi < 4; ++mi)
                ldsm4(af[mi], abuf + mi * 2048 + ksa);
            uint32_t bf[2][4];
            #pragma unroll
            for (int p = 0; p < 2; ++p)
                ldsm4(bf[p], bbuf + p * 2048 + ksb);
            #pragma unroll
            for (int p = 0; p < 2; ++p) {
                #pragma unroll
                for (int mi = 0; mi < 4; ++mi)
                    mma_f16(acc[mi][2 * p], af[mi], &bf[p][0]);
                #pragma unroll
                for (int mi = 0; mi < 4; ++mi)
                    mma_f16(acc[mi][2 * p + 1], af[mi], &bf[p][2]);
            }
        }
        __syncthreads();
    }

    // ---- epilogue ----
    const int c2 = (lane & 3) * 2;
    #pragma unroll
    for (int mi = 0; mi < 4; ++mi) {
        #pragma unroll
        for (int rr = 0; rr < 2; ++rr) {
            int m = bm0 + wm0 + mi * 16 + rm + rr * 8;
            #pragma unroll
            for (int ni = 0; ni < 4; ++ni) {
                int n = bn0 + wn0 + ni * 8 + c2;
                float p0 = acc[mi][ni][rr * 2 + 0] + bias[n];
                float p1 = acc[mi][ni][rr * 2 + 1] + bias[n + 1];
                if (EPI == 0) {
                    float s0 = sigf(p0), s1 = sigf(p1);
                    if (n < GG) {
                        float2 z; z.x = 0.875f * s0 + 0.125f; z.y = 0.875f * s1 + 0.125f;
                        *(float2*)&g_Z[(size_t)m * GG + n] = z;
                    } else {
                        size_t j = (size_t)m * GG + (n - GG);
                        float2 ha = *(const float2*)&g_HA[j];     // f32 master
                        // single rounding: f32 product -> f16
                        *(__half2*)&g_HBH[j] =
                            __floats2half2_rn(s0 * ha.x, s1 * ha.y);
                    }
                } else {
                    size_t zj = (size_t)m * GG + n;
                    float2 zv = *(const float2*)&g_Z[zj];
                    int2 hv = *(const int2*)&hidden[(size_t)m * HS + hoff + n];
                    float2 recf, ohf;
                    hupd(p0, zv.x, hv.x, &recf.x, &ohf.x);
                    hupd(p1, zv.y, hv.y, &recf.y, &ohf.y);
                    *(float2*)&out[(size_t)m * HS + hoff + n] = recf;
                    *(float2*)&out[(size_t)BATCH * HS + (size_t)m * HS + hoff + n] = ohf;
                    if (writeHA) {
                        *(float2*)&g_HA[zj] = ohf;                       // f32 master
                        *(__half2*)&g_HAH[zj] = __floats2half2_rn(ohf.x, ohf.y);
                    }
                }
            }
        }
    }
}

// ---------------- aux kernels ----------------
// WTH[n][k] = f16(W[k][n])
__global__ void transpose_k(const float* __restrict__ W, int N) {
    __shared__ float t[32][33];
    int n0 = blockIdx.x * 32, k0 = blockIdx.y * 32;
    int tx = threadIdx.x, ty = threadIdx.y;   // 32 x 8
    #pragma unroll
    for (int i = 0; i < 32; i += 8)
        t[ty + i][tx] = W[(size_t)(k0 + ty + i) * N + n0 + tx];
    __syncthreads();
    #pragma unroll
    for (int i = 0; i < 32; i += 8)
        g_WTH[(size_t)(n0 + ty + i) * KTOT + k0 + tx] = __float2half_rn(t[tx][ty + i]);
}

// x -> f16
__global__ void x2h_k(const float* __restrict__ x) {
    size_t N4 = (size_t)BATCH * INS / 4;
    for (size_t i = (size_t)blockIdx.x * blockDim.x + threadIdx.x; i < N4;
         i += (size_t)gridDim.x * blockDim.x) {
        float4 v = *(const float4*)&x[i * 4];
        __half2 h0 = __floats2half2_rn(v.x, v.y);
        __half2 h1 = __floats2half2_rn(v.z, v.w);
        *(__half2*)&g_XH[i * 4]     = h0;
        *(__half2*)&g_XH[i * 4 + 2] = h1;
    }
}

// HA(f32) + HAH(f16) = h2_fl = hidden[:, G:] / 2^23
__global__ void prep_k(const int* __restrict__ hidden) {
    size_t N4 = (size_t)BATCH * GG / 4;
    for (size_t i = (size_t)blockIdx.x * blockDim.x + threadIdx.x; i < N4;
         i += (size_t)gridDim.x * blockDim.x) {
        size_t row = i >> 8;
        int c4 = (int)(i & 255) * 4;
        int4 h = *(const int4*)&hidden[row * HS + GG + c4];
        float4 f;
        f.x = (float)h.x * (1.0f / 8388608.0f);
        f.y = (float)h.y * (1.0f / 8388608.0f);
        f.z = (float)h.z * (1.0f / 8388608.0f);
        f.w = (float)h.w * (1.0f / 8388608.0f);
        *(float4*)&g_HA[i * 4] = f;
        *(__half2*)&g_HAH[i * 4]     = __floats2half2_rn(f.x, f.y);
        *(__half2*)&g_HAH[i * 4 + 2] = __floats2half2_rn(f.z, f.w);
    }
}

__global__ void bits_k(const int* __restrict__ slice_ptr, int which) {
    const int slice = slice_ptr ? __ldg(slice_ptr) : 0;
    float s = 0.0f;
    size_t N4 = (size_t)BATCH * GG / 4;
    for (size_t i = (size_t)blockIdx.x * blockDim.x + threadIdx.x; i < N4;
         i += (size_t)gridDim.x * blockDim.x) {
        int col = (int)(i & 255) * 4;
        float4 z = *(const float4*)&g_Z[i * 4];
        if (col     >= slice) s -= log2f(z.x);
        if (col + 1 >= slice) s -= log2f(z.y);
        if (col + 2 >= slice) s -= log2f(z.z);
        if (col + 3 >= slice) s -= log2f(z.w);
    }
    #pragma unroll
    for (int o = 16; o > 0; o >>= 1)
        s += __shfl_down_sync(0xFFFFFFFFu, s, o);
    __shared__ double sm[8];
    int wid = threadIdx.x >> 5, lane = threadIdx.x & 31;
    if (lane == 0) sm[wid] = (double)s;
    __syncthreads();
    if (threadIdx.x == 0) {
        double t = 0.0;
        #pragma unroll
        for (int i = 0; i < 8; ++i) t += sm[i];
        if (which) g_bp2[blockIdx.x] = t;
        else       g_bp1[blockIdx.x] = t;
    }
}

__global__ void final_k(float* __restrict__ out, const int* __restrict__ slice_ptr) {
    __shared__ double sm[256];
    double s = 0.0;
    for (int i = threadIdx.x; i < 512; i += 256) s += g_bp1[i] + g_bp2[i];
    sm[threadIdx.x] = s;
    __syncthreads();
    for (int o = 128; o > 0; o >>= 1) {
        if (threadIdx.x < (unsigned)o) sm[threadIdx.x] += sm[threadIdx.x + o];
        __syncthreads();
    }
    if (threadIdx.x == 0) {
        int slice = slice_ptr ? slice_ptr[0] : 0;
        out[(size_t)2 * BATCH * HS] =
            (float)(sm[0] + 32.0 * (double)slice * (double)BATCH);
    }
}

extern "C" void kernel_launch(void* const* d_in, const int* in_sizes, int n_in,
                              void* d_out, int out_size) {
    (void)in_sizes; (void)out_size;
    const float* x      = (const float*)d_in[0];
    const int*   hidden = (const int*)d_in[1];
    const float* Wzr1   = (const float*)d_in[2];
    const float* bzr1   = (const float*)d_in[3];
    const float* Wg1    = (const float*)d_in[4];
    const float* bg1    = (const float*)d_in[5];
    const float* Wzr2   = (const float*)d_in[6];
    const float* bzr2   = (const float*)d_in[7];
    const float* Wg2    = (const float*)d_in[8];
    const float* bg2    = (const float*)d_in[9];
    const int*   slice  = (n_in > 10) ? (const int*)d_in[10] : nullptr;
    float* out = (float*)d_out;

    cudaFuncSetAttribute(gemm_tc<0>, cudaFuncAttributeMaxDynamicSharedMemorySize, SMEM_TOTAL);
    cudaFuncSetAttribute(gemm_tc<1>, cudaFuncAttributeMaxDynamicSharedMemorySize, SMEM_TOTAL);

    prep_k<<<2048, 256>>>(hidden);                                   // 0
    x2h_k<<<2048, 256>>>(x);                                         // 1
    transpose_k<<<dim3(64, 64), dim3(32, 8)>>>(Wzr1, HS);            // 2

    // zr1: z1 -> g_Z, HBH = f16(r1 * h2_fl)
    gemm_tc<0><<<dim3(HS / BN, BATCH / BM), NTHR, SMEM_TOTAL>>>(     // 3 (profiled)
        bzr1, 0, nullptr, 0, nullptr, 0);
    bits_k<<<512, 256>>>(slice, 0);                                  // 4

    // g1: h1 update; rec/out cols [0,1024); HA/HAH = h1_fl
    transpose_k<<<dim3(32, 64), dim3(32, 8)>>>(Wg1, GG);             // 5
    gemm_tc<1><<<dim3(GG / BN, BATCH / BM), NTHR, SMEM_TOTAL>>>(     // 6
        bg1, 1, hidden, 0, out, 1);

    // zr2
    transpose_k<<<dim3(64, 64), dim3(32, 8)>>>(Wzr2, HS);            // 7
    gemm_tc<0><<<dim3(HS / BN, BATCH / BM), NTHR, SMEM_TOTAL>>>(     // 8
        bzr2, 0, nullptr, 0, nullptr, 0);
    bits_k<<<512, 256>>>(nullptr, 1);                                // 9

    // g2
    transpose_k<<<dim3(32, 64), dim3(32, 8)>>>(Wg2, GG);             // 10
    gemm_tc<1><<<dim3(GG / BN, BATCH / BM), NTHR, SMEM_TOTAL>>>(     // 11
        bg2, 1, hidden, 1024, out, 0);

    final_k<<<1, 256>>>(out, slice);                                 // 12
}

// round 17
// speedup vs baseline: 2.0809x; 1.1791x over previous
#include <cuda_runtime.h>
#include <cuda_fp16.h>
#include <cstdint>

typedef long long ll;

#define BATCH 8192
#define INS   1024          // K-halves from x
#define GG    1024
#define HS    2048
#define KTOT  2048          // total K (halves)

#define BM 128
#define BN 128
#define BK 64               // halves per stage = 128B rows
#define NKI (KTOT/BK)       // 32 K-stages
#define STAGES 3
#define NTHR 256            // 8 warps: 2(M) x 4(N), warp tile 64x32

#define A_BYTES (BM*BK*2)   // 16384
#define B_BYTES (BN*BK*2)   // 16384
#define A_OFF  1024
#define B_OFF  (A_OFF + STAGES*A_BYTES)
#define SMEM_TOTAL (B_OFF + STAGES*B_BYTES)   // 99328 -> 2 CTAs/SM

#define SW(o) ((o) ^ (((o)>>3)&0x70))

// ---------------- scratch ----------------
__device__ float  g_HA [(size_t)BATCH * GG];   // f32 master: h2_fl, later h1_fl
__device__ __half g_HAH[(size_t)BATCH * GG];   // f16 mirror for GEMM A-loads
__device__ __half g_HBH[(size_t)BATCH * GG];   // f16: r * h_fl (single rounding)
__device__ __half g_XH [(size_t)BATCH * INS];  // f16 x
__device__ float  g_Z  [(size_t)BATCH * GG];   // z1, later z2
__device__ __half g_WTH[(size_t)KTOT * HS];    // transposed weight [N][K] f16
__device__ double g_bp1[512];
__device__ double g_bp2[512];

// ---------------- helpers ----------------
__device__ __forceinline__ uint32_t smaddr(const void* p) {
    return (uint32_t)__cvta_generic_to_shared(p);
}
__device__ __forceinline__ void cp16(uint32_t d, const void* s) {
    asm volatile("cp.async.cg.shared.global [%0], [%1], 16;\n" :: "r"(d), "l"(s));
}
__device__ __forceinline__ void cpcommit() { asm volatile("cp.async.commit_group;\n" ::); }
template<int N> __device__ __forceinline__ void cpwait() {
    asm volatile("cp.async.wait_group %0;\n" :: "n"(N));
}

// ldmatrix x4: 4 8x8-b16 matrices; thread t gets (row t/4, half-pair t%4)
__device__ __forceinline__ void ldsm4(uint32_t* r, uint32_t addr) {
    asm volatile("ldmatrix.sync.aligned.m8n8.x4.shared.b16 {%0,%1,%2,%3}, [%4];"
        : "=r"(r[0]), "=r"(r[1]), "=r"(r[2]), "=r"(r[3]) : "r"(addr));
}

// f16 inputs, f32 accumulate (K=16 per HMMA)
__device__ __forceinline__ void mma_f16(float* d, const uint32_t* a, const uint32_t* b) {
    asm volatile(
        "mma.sync.aligned.m16n8k16.row.col.f32.f16.f16.f32 "
        "{%0,%1,%2,%3}, {%4,%5,%6,%7}, {%8,%9}, {%0,%1,%2,%3};\n"
        : "+f"(d[0]), "+f"(d[1]), "+f"(d[2]), "+f"(d[3])
        : "r"(a[0]), "r"(a[1]), "r"(a[2]), "r"(a[3]), "r"(b[0]), "r"(b[1]));
}

__device__ __forceinline__ float sigf(float v) { return 1.0f / (1.0f + expf(-v)); }
__device__ __forceinline__ void hupd(float pre, float z, int h, float* rec, float* oh) {
    float gv = tanhf(pre);
    ll zf = (ll)(z * 1024.0f); if (zf < 1) zf = 1;
    int hi = (int)((((ll)h * zf) >> 10) + (ll)((1.0f - z) * gv * 8388608.0f));
    *rec = (float)hi; *oh = (float)hi * (1.0f / 8388608.0f);
}

// ---------------- GEMM (f16 operands, f32 accum; 2 CTAs/SM) ----------------
template<int EPI>
__global__ void __launch_bounds__(NTHR, 2) gemm_tc(
    const float* __restrict__ bias,
    int hinSel,
    const int* __restrict__ hidden,
    int hoff,
    float* __restrict__ out,
    int writeHA)
{
    extern __shared__ char smem[];
    const uint32_t sbase = smaddr(smem);
    const int tid  = threadIdx.x;
    const int wid  = tid >> 5, lane = tid & 31;
    const int bm0  = blockIdx.y * BM;
    const int bn0  = blockIdx.x * BN;
    const __half* HinH = hinSel ? g_HBH : g_HAH;

    auto load_stage = [&](int kt, int buf) {
        const int kbase = kt * BK;
        const __half* asrc = (kbase < INS) ? (g_XH + kbase) : (HinH + (kbase - INS));
        const uint32_t abase = sbase + A_OFF + buf * A_BYTES;
        #pragma unroll
        for (int i = 0; i < 4; ++i) {
            int q = tid + i * NTHR;
            int row = q >> 3, kc = q & 7;
            uint32_t off = row * 128 + kc * 16;
            cp16(abase + SW(off), asrc + (size_t)(bm0 + row) * INS + kc * 8);
        }
        const uint32_t bbase = sbase + B_OFF + buf * B_BYTES;
        #pragma unroll
        for (int i = 0; i < 4; ++i) {
            int q = tid + i * NTHR;
            int row = q >> 3, kc = q & 7;
            uint32_t off = row * 128 + kc * 16;
            cp16(bbase + SW(off), g_WTH + (size_t)(bn0 + row) * KTOT + kbase + kc * 8);
        }
    };

    #pragma unroll
    for (int s = 0; s < STAGES - 1; ++s) { load_stage(s, s); cpcommit(); }

    // 8 warps: 2(M) x 4(N); warp tile 64x32
    const int wm0 = (wid >> 2) * 64;
    const int wn0 = (wid & 3) * 32;
    const int rm = lane >> 2;

    // ldmatrix lane roles (chunks are 8 halves = 16B)
    const int r8   = lane & 7;
    const int gsel = lane >> 3;
    const int a_row = wm0 + r8 + ((gsel & 1) << 3);
    const uint32_t a_kx = (uint32_t)((gsel >> 1) << 4);
    const int b_row = wn0 + r8 + ((gsel >> 1) << 3);
    const uint32_t b_kx = (uint32_t)((gsel & 1) << 4);
    const uint32_t lsw = (uint32_t)(r8 << 4);
    const uint32_t aAddr0 = sbase + A_OFF + (uint32_t)(a_row * 128);
    const uint32_t bAddr0 = sbase + B_OFF + (uint32_t)(b_row * 128);

    float acc[4][4][4];
    #pragma unroll
    for (int i = 0; i < 4; ++i)
        #pragma unroll
        for (int j = 0; j < 4; ++j)
            #pragma unroll
            for (int e = 0; e < 4; ++e) acc[i][j][e] = 0.0f;

    int buf = 0;                       // stage kt resides in buffer buf
    for (int kt = 0; kt < NKI; ++kt) {
        const int lt = kt + STAGES - 1;
        const int lbuf = (buf + STAGES - 1) % STAGES;
        if (lt < NKI) load_stage(lt, lbuf);
        cpcommit();
        cpwait<STAGES - 1>();
        __syncthreads();

        const uint32_t abuf = aAddr0 + buf * A_BYTES;
        const uint32_t bbuf = bAddr0 + buf * B_BYTES;
        #pragma unroll
        for (int ks = 0; ks < 4; ++ks) {        // K=16 halves per ks
            const uint32_t ksa = ((uint32_t)(ks * 32) + a_kx) ^ lsw;
            const uint32_t ksb = ((uint32_t)(ks * 32) + b_kx) ^ lsw;
            uint32_t af[4][4];
            #pragma unroll
            for (int mi = 0; mi < 4; ++mi)
                ldsm4(af[mi], abuf + mi * 2048 + ksa);
            uint32_t bf[2][4];
            #pragma unroll
            for (int p = 0; p < 2; ++p)
                ldsm4(bf[p], bbuf + p * 2048 + ksb);
            #pragma unroll
            for (int p = 0; p < 2; ++p) {
                #pragma unroll
                for (int mi = 0; mi < 4; ++mi)
                    mma_f16(acc[mi][2 * p], af[mi], &bf[p][0]);
                #pragma unroll
                for (int mi = 0; mi < 4; ++mi)
                    mma_f16(acc[mi][2 * p + 1], af[mi], &bf[p][2]);
            }
        }
        __syncthreads();
        buf = (buf + 1 == STAGES) ? 0 : buf + 1;
    }

    // ---- epilogue ----
    const int c2 = (lane & 3) * 2;
    #pragma unroll
    for (int mi = 0; mi < 4; ++mi) {
        #pragma unroll
        for (int rr = 0; rr < 2; ++rr) {
            int m = bm0 + wm0 + mi * 16 + rm + rr * 8;
            #pragma unroll
            for (int ni = 0; ni < 4; ++ni) {
                int n = bn0 + wn0 + ni * 8 + c2;
                float p0 = acc[mi][ni][rr * 2 + 0] + bias[n];
                float p1 = acc[mi][ni][rr * 2 + 1] + bias[n + 1];
                if (EPI == 0) {
                    float s0 = sigf(p0), s1 = sigf(p1);
                    if (n < GG) {
                        float2 z; z.x = 0.875f * s0 + 0.125f; z.y = 0.875f * s1 + 0.125f;
                        *(float2*)&g_Z[(size_t)m * GG + n] = z;
                    } else {
                        size_t j = (size_t)m * GG + (n - GG);
                        float2 ha = *(const float2*)&g_HA[j];
                        *(__half2*)&g_HBH[j] =
                            __floats2half2_rn(s0 * ha.x, s1 * ha.y);
                    }
                } else {
                    size_t zj = (size_t)m * GG + n;
                    float2 zv = *(const float2*)&g_Z[zj];
                    int2 hv = *(const int2*)&hidden[(size_t)m * HS + hoff + n];
                    float2 recf, ohf;
                    hupd(p0, zv.x, hv.x, &recf.x, &ohf.x);
                    hupd(p1, zv.y, hv.y, &recf.y, &ohf.y);
                    *(float2*)&out[(size_t)m * HS + hoff + n] = recf;
                    *(float2*)&out[(size_t)BATCH * HS + (size_t)m * HS + hoff + n] = ohf;
                    if (writeHA) {
                        *(float2*)&g_HA[zj] = ohf;
                        *(__half2*)&g_HAH[zj] = __floats2half2_rn(ohf.x, ohf.y);
                    }
                }
            }
        }
    }
}

// ---------------- aux kernels ----------------
// WTH[n][k] = f16(W[k][n])
__global__ void transpose_k(const float* __restrict__ W, int N) {
    __shared__ float t[32][33];
    int n0 = blockIdx.x * 32, k0 = blockIdx.y * 32;
    int tx = threadIdx.x, ty = threadIdx.y;   // 32 x 8
    #pragma unroll
    for (int i = 0; i < 32; i += 8)
        t[ty + i][tx] = W[(size_t)(k0 + ty + i) * N + n0 + tx];
    __syncthreads();
    #pragma unroll
    for (int i = 0; i < 32; i += 8)
        g_WTH[(size_t)(n0 + ty + i) * KTOT + k0 + tx] = __float2half_rn(t[tx][ty + i]);
}

// x -> f16
__global__ void x2h_k(const float* __restrict__ x) {
    size_t N4 = (size_t)BATCH * INS / 4;
    for (size_t i = (size_t)blockIdx.x * blockDim.x + threadIdx.x; i < N4;
         i += (size_t)gridDim.x * blockDim.x) {
        float4 v = *(const float4*)&x[i * 4];
        *(__half2*)&g_XH[i * 4]     = __floats2half2_rn(v.x, v.y);
        *(__half2*)&g_XH[i * 4 + 2] = __floats2half2_rn(v.z, v.w);
    }
}

// HA(f32) + HAH(f16) = h2_fl = hidden[:, G:] / 2^23
__global__ void prep_k(const int* __restrict__ hidden) {
    size_t N4 = (size_t)BATCH * GG / 4;
    for (size_t i = (size_t)blockIdx.x * blockDim.x + threadIdx.x; i < N4;
         i += (size_t)gridDim.x * blockDim.x) {
        size_t row = i >> 8;
        int c4 = (int)(i & 255) * 4;
        int4 h = *(const int4*)&hidden[row * HS + GG + c4];
        float4 f;
        f.x = (float)h.x * (1.0f / 8388608.0f);
        f.y = (float)h.y * (1.0f / 8388608.0f);
        f.z = (float)h.z * (1.0f / 8388608.0f);
        f.w = (float)h.w * (1.0f / 8388608.0f);
        *(float4*)&g_HA[i * 4] = f;
        *(__half2*)&g_HAH[i * 4]     = __floats2half2_rn(f.x, f.y);
        *(__half2*)&g_HAH[i * 4 + 2] = __floats2half2_rn(f.z, f.w);
    }
}

__global__ void bits_k(const int* __restrict__ slice_ptr, int which) {
    const int slice = slice_ptr ? __ldg(slice_ptr) : 0;
    float s = 0.0f;
    size_t N4 = (size_t)BATCH * GG / 4;
    for (size_t i = (size_t)blockIdx.x * blockDim.x + threadIdx.x; i < N4;
         i += (size_t)gridDim.x * blockDim.x) {
        int col = (int)(i & 255) * 4;
        float4 z = *(const float4*)&g_Z[i * 4];
        if (col     >= slice) s -= log2f(z.x);
        if (col + 1 >= slice) s -= log2f(z.y);
        if (col + 2 >= slice) s -= log2f(z.z);
        if (col + 3 >= slice) s -= log2f(z.w);
    }
    #pragma unroll
    for (int o = 16; o > 0; o >>= 1)
        s += __shfl_down_sync(0xFFFFFFFFu, s, o);
    __shared__ double sm[8];
    int wid = threadIdx.x >> 5, lane = threadIdx.x & 31;
    if (lane == 0) sm[wid] = (double)s;
    __syncthreads();
    if (threadIdx.x == 0) {
        double t = 0.0;
        #pragma unroll
        for (int i = 0; i < 8; ++i) t += sm[i];
        if (which) g_bp2[blockIdx.x] = t;
        else       g_bp1[blockIdx.x] = t;
    }
}

__global__ void final_k(float* __restrict__ out, const int* __restrict__ slice_ptr) {
    __shared__ double sm[256];
    double s = 0.0;
    for (int i = threadIdx.x; i < 512; i += 256) s += g_bp1[i] + g_bp2[i];
    sm[threadIdx.x] = s;
    __syncthreads();
    for (int o = 128; o > 0; o >>= 1) {
        if (threadIdx.x < (unsigned)o) sm[threadIdx.x] += sm[threadIdx.x + o];
        __syncthreads();
    }
    if (threadIdx.x == 0) {
        int slice = slice_ptr ? slice_ptr[0] : 0;
        out[(size_t)2 * BATCH * HS] =
            (float)(sm[0] + 32.0 * (double)slice * (double)BATCH);
    }
}

extern "C" void kernel_launch(void* const* d_in, const int* in_sizes, int n_in,
                              void* d_out, int out_size) {
    (void)in_sizes; (void)out_size;
    const float* x      = (const float*)d_in[0];
    const int*   hidden = (const int*)d_in[1];
    const float* Wzr1   = (const float*)d_in[2];
    const float* bzr1   = (const float*)d_in[3];
    const float* Wg1    = (const float*)d_in[4];
    const float* bg1    = (const float*)d_in[5];
    const float* Wzr2   = (const float*)d_in[6];
    const float* bzr2   = (const float*)d_in[7];
    const float* Wg2    = (const float*)d_in[8];
    const float* bg2    = (const float*)d_in[9];
    const int*   slice  = (n_in > 10) ? (const int*)d_in[10] : nullptr;
    float* out = (float*)d_out;

    cudaFuncSetAttribute(gemm_tc<0>, cudaFuncAttributeMaxDynamicSharedMemorySize, SMEM_TOTAL);
    cudaFuncSetAttribute(gemm_tc<1>, cudaFuncAttributeMaxDynamicSharedMemorySize, SMEM_TOTAL);

    prep_k<<<2048, 256>>>(hidden);                                   // 0
    x2h_k<<<2048, 256>>>(x);                                         // 1
    transpose_k<<<dim3(64, 64), dim3(32, 8)>>>(Wzr1, HS);            // 2

    // zr1: z1 -> g_Z, HBH = f16(r1 * h2_fl)
    gemm_tc<0><<<dim3(HS / BN, BATCH / BM), NTHR, SMEM_TOTAL>>>(     // 3 (profiled)
        bzr1, 0, nullptr, 0, nullptr, 0);
    bits_k<<<512, 256>>>(slice, 0);                                  // 4

    // g1: h1 update; rec/out cols [0,1024); HA/HAH = h1_fl
    transpose_k<<<dim3(32, 64), dim3(32, 8)>>>(Wg1, GG);             // 5
    gemm_tc<1><<<dim3(GG / BN, BATCH / BM), NTHR, SMEM_TOTAL>>>(     // 6
        bg1, 1, hidden, 0, out, 1);

    // zr2
    transpose_k<<<dim3(64, 64), dim3(32, 8)>>>(Wzr2, HS);            // 7
    gemm_tc<0><<<dim3(HS / BN, BATCH / BM), NTHR, SMEM_TOTAL>>>(     // 8
        bzr2, 0, nullptr, 0, nullptr, 0);
    bits_k<<<512, 256>>>(nullptr, 1);                                // 9

    // g2
    transpose_k<<<dim3(32, 64), dim3(32, 8)>>>(Wg2, GG);             // 10
    gemm_tc<1><<<dim3(GG / BN, BATCH / BM), NTHR, SMEM_TOTAL>>>(     // 11
        bg2, 1, hidden, 1024, out, 0);

    final_k<<<1, 256>>>(out, slice);                                 // 12
}